// round 1
// baseline (speedup 1.0000x reference)
#include <cuda_runtime.h>
#include <cuda_bf16.h>
#include <math.h>

// Problem constants (fixed by dataset)
#define B_C   4
#define L_C   2048
#define EMB_C 1024
#define HEADS_C 16
#define DH    64
#define MROWS (B_C * L_C)          // 8192
#define SCALE_C 0.125f             // 1/sqrt(64)

// ---------------------------------------------------------------------------
// Scratch (allocation-free rule: __device__ globals)
// ---------------------------------------------------------------------------
__device__ float g_q[MROWS * EMB_C];
__device__ float g_k[MROWS * EMB_C];
__device__ float g_v[MROWS * EMB_C];
__device__ float g_att[MROWS * EMB_C];

// ---------------------------------------------------------------------------
// SGEMM: C[M,N] = A[M,K] @ W[K,N] + bias[N]
// 128x128x16 tile, 256 threads, 8x8 per thread (split 4 + 64+4 fragments so
// all compute-phase LDS are conflict-free LDS.128 / broadcast).
// ---------------------------------------------------------------------------
__global__ __launch_bounds__(256)
void gemm_bias_kernel(const float* __restrict__ A, const float* __restrict__ W,
                      const float* __restrict__ bias, float* __restrict__ C,
                      int M, int N, int K) {
    __shared__ float As[16 * 128];   // [kk][m] (transposed)
    __shared__ float Bs[16 * 128];   // [kk][n]

    const int tid = threadIdx.x;
    const int m0 = blockIdx.y * 128;
    const int n0 = blockIdx.x * 128;
    const int tx = tid & 15;
    const int ty = tid >> 4;

    const int arow = tid >> 2;            // 0..63
    const int acol = (tid & 3) << 2;      // 0,4,8,12
    const int brow = tid >> 5;            // 0..7
    const int bcol = (tid & 31) << 2;     // 0..124

    float acc[8][8];
#pragma unroll
    for (int i = 0; i < 8; i++)
#pragma unroll
        for (int j = 0; j < 8; j++) acc[i][j] = 0.f;

    for (int k0 = 0; k0 < K; k0 += 16) {
        float4 a0 = *(const float4*)&A[(size_t)(m0 + arow) * K + k0 + acol];
        float4 a1 = *(const float4*)&A[(size_t)(m0 + arow + 64) * K + k0 + acol];
        float4 b0 = *(const float4*)&W[(size_t)(k0 + brow) * N + n0 + bcol];
        float4 b1 = *(const float4*)&W[(size_t)(k0 + brow + 8) * N + n0 + bcol];
        __syncthreads();
        As[(acol + 0) * 128 + arow] = a0.x;
        As[(acol + 1) * 128 + arow] = a0.y;
        As[(acol + 2) * 128 + arow] = a0.z;
        As[(acol + 3) * 128 + arow] = a0.w;
        As[(acol + 0) * 128 + arow + 64] = a1.x;
        As[(acol + 1) * 128 + arow + 64] = a1.y;
        As[(acol + 2) * 128 + arow + 64] = a1.z;
        As[(acol + 3) * 128 + arow + 64] = a1.w;
        *(float4*)&Bs[brow * 128 + bcol] = b0;
        *(float4*)&Bs[(brow + 8) * 128 + bcol] = b1;
        __syncthreads();
#pragma unroll
        for (int kk = 0; kk < 16; kk++) {
            float4 af0 = *(float4*)&As[kk * 128 + ty * 4];
            float4 af1 = *(float4*)&As[kk * 128 + 64 + ty * 4];
            float4 bf0 = *(float4*)&Bs[kk * 128 + tx * 4];
            float4 bf1 = *(float4*)&Bs[kk * 128 + 64 + tx * 4];
            float a[8] = {af0.x, af0.y, af0.z, af0.w, af1.x, af1.y, af1.z, af1.w};
            float b[8] = {bf0.x, bf0.y, bf0.z, bf0.w, bf1.x, bf1.y, bf1.z, bf1.w};
#pragma unroll
            for (int i = 0; i < 8; i++)
#pragma unroll
                for (int j = 0; j < 8; j++) acc[i][j] = fmaf(a[i], b[j], acc[i][j]);
        }
    }

    float4 bv0 = *(const float4*)&bias[n0 + tx * 4];
    float4 bv1 = *(const float4*)&bias[n0 + 64 + tx * 4];
    float bb[8] = {bv0.x, bv0.y, bv0.z, bv0.w, bv1.x, bv1.y, bv1.z, bv1.w};
#pragma unroll
    for (int i = 0; i < 8; i++) {
        int r = m0 + ((i < 4) ? (ty * 4 + i) : (64 + ty * 4 + i - 4));
        float4 o0 = make_float4(acc[i][0] + bb[0], acc[i][1] + bb[1],
                                acc[i][2] + bb[2], acc[i][3] + bb[3]);
        float4 o1 = make_float4(acc[i][4] + bb[4], acc[i][5] + bb[5],
                                acc[i][6] + bb[6], acc[i][7] + bb[7]);
        *(float4*)&C[(size_t)r * N + n0 + tx * 4] = o0;
        *(float4*)&C[(size_t)r * N + n0 + 64 + tx * 4] = o1;
    }
}

// ---------------------------------------------------------------------------
// Flash attention (causal), fp32. BM=BN=64, D=64, 256 threads.
// Thread (tx,ty) owns score sub-tile rows ty*4..+3, cols tx*4..+3.
// sQ/sK stored transposed [kk][row], stride 68 (16B-aligned, conflict-free).
// Online softmax state per thread: m[4], l[4], acc[4][4] (d = tx*4..+3).
// ---------------------------------------------------------------------------
__global__ __launch_bounds__(256)
void attn_kernel(const float* __restrict__ q, const float* __restrict__ k,
                 const float* __restrict__ v, float* __restrict__ out) {
    extern __shared__ float smem[];
    float* sQ = smem;                 // 64*68  [kk][r]
    float* sK = smem + 64 * 68;       // 64*68  [kk][c]
    float* sV = smem + 2 * 64 * 68;   // 64*68  [c][d]
    float* sP = smem + 3 * 64 * 68;   // 64*68  [r][c]

    const int tid = threadIdx.x;
    const int m0 = blockIdx.x * 64;
    const int h  = blockIdx.y;
    const int b  = blockIdx.z;
    const int tx = tid & 15;
    const int ty = tid >> 4;

    const size_t baseOff = (size_t)b * L_C * EMB_C + (size_t)h * DH;
    const float* qb = q + baseOff;
    const float* kb = k + baseOff;
    const float* vb = v + baseOff;

    // Load Q tile transposed + pre-scaled (done once per block)
    {
        int r   = tid & 63;
        int kk0 = (tid >> 6) << 4;
        const float* src = qb + (size_t)(m0 + r) * EMB_C;
#pragma unroll
        for (int c = 0; c < 4; c++) {
            float4 g = *(const float4*)&src[kk0 + c * 4];
            sQ[(kk0 + c * 4 + 0) * 68 + r] = g.x * SCALE_C;
            sQ[(kk0 + c * 4 + 1) * 68 + r] = g.y * SCALE_C;
            sQ[(kk0 + c * 4 + 2) * 68 + r] = g.z * SCALE_C;
            sQ[(kk0 + c * 4 + 3) * 68 + r] = g.w * SCALE_C;
        }
    }

    float m_i[4], l_i[4], acc[4][4];
#pragma unroll
    for (int i = 0; i < 4; i++) {
        m_i[i] = -INFINITY;
        l_i[i] = 0.f;
#pragma unroll
        for (int j = 0; j < 4; j++) acc[i][j] = 0.f;
    }

    for (int n0 = 0; n0 <= m0; n0 += 64) {
        __syncthreads();  // previous iteration's PV reads done
        // Load K tile transposed
        {
            int r   = tid & 63;
            int kk0 = (tid >> 6) << 4;
            const float* src = kb + (size_t)(n0 + r) * EMB_C;
#pragma unroll
            for (int c = 0; c < 4; c++) {
                float4 g = *(const float4*)&src[kk0 + c * 4];
                sK[(kk0 + c * 4 + 0) * 68 + r] = g.x;
                sK[(kk0 + c * 4 + 1) * 68 + r] = g.y;
                sK[(kk0 + c * 4 + 2) * 68 + r] = g.z;
                sK[(kk0 + c * 4 + 3) * 68 + r] = g.w;
            }
        }
        // Load V tile natural [c][d]
        {
            int row = tid >> 2;
            int c0  = (tid & 3) << 4;
            const float* src = vb + (size_t)(n0 + row) * EMB_C;
#pragma unroll
            for (int j4 = 0; j4 < 4; j4++) {
                float4 g = *(const float4*)&src[c0 + j4 * 4];
                *(float4*)&sV[row * 68 + c0 + j4 * 4] = g;
            }
        }
        __syncthreads();

        // ---- scores: s = (Q*SCALE) . K^T ----
        float s[4][4];
#pragma unroll
        for (int i = 0; i < 4; i++)
#pragma unroll
            for (int j = 0; j < 4; j++) s[i][j] = 0.f;
#pragma unroll
        for (int kk = 0; kk < 64; kk++) {
            float4 qf = *(float4*)&sQ[kk * 68 + ty * 4];
            float4 kf = *(float4*)&sK[kk * 68 + tx * 4];
            float a[4] = {qf.x, qf.y, qf.z, qf.w};
            float c[4] = {kf.x, kf.y, kf.z, kf.w};
#pragma unroll
            for (int i = 0; i < 4; i++)
#pragma unroll
                for (int j = 0; j < 4; j++) s[i][j] = fmaf(a[i], c[j], s[i][j]);
        }

        // causal mask only needed on the diagonal tile
        if (n0 == m0) {
#pragma unroll
            for (int i = 0; i < 4; i++)
#pragma unroll
                for (int j = 0; j < 4; j++)
                    if (tx * 4 + j > ty * 4 + i) s[i][j] = -INFINITY;
        }

        // ---- online softmax ----
#pragma unroll
        for (int i = 0; i < 4; i++) {
            float tm = fmaxf(fmaxf(s[i][0], s[i][1]), fmaxf(s[i][2], s[i][3]));
#pragma unroll
            for (int off = 8; off > 0; off >>= 1)
                tm = fmaxf(tm, __shfl_xor_sync(0xffffffffu, tm, off));
            float mn = fmaxf(m_i[i], tm);
            float f  = __expf(m_i[i] - mn);
            float rs = 0.f;
#pragma unroll
            for (int j = 0; j < 4; j++) {
                s[i][j] = __expf(s[i][j] - mn);
                rs += s[i][j];
            }
#pragma unroll
            for (int off = 8; off > 0; off >>= 1)
                rs += __shfl_xor_sync(0xffffffffu, rs, off);
            l_i[i] = l_i[i] * f + rs;
            m_i[i] = mn;
#pragma unroll
            for (int j = 0; j < 4; j++) acc[i][j] *= f;
        }

        // ---- publish P, then PV ----
#pragma unroll
        for (int i = 0; i < 4; i++)
            *(float4*)&sP[(ty * 4 + i) * 68 + tx * 4] =
                make_float4(s[i][0], s[i][1], s[i][2], s[i][3]);
        __syncthreads();

#pragma unroll 8
        for (int col = 0; col < 64; col++) {
            float4 vv = *(float4*)&sV[col * 68 + tx * 4];
#pragma unroll
            for (int i = 0; i < 4; i++) {
                float pr = sP[(ty * 4 + i) * 68 + col];
                acc[i][0] = fmaf(pr, vv.x, acc[i][0]);
                acc[i][1] = fmaf(pr, vv.y, acc[i][1]);
                acc[i][2] = fmaf(pr, vv.z, acc[i][2]);
                acc[i][3] = fmaf(pr, vv.w, acc[i][3]);
            }
        }
    }

    // epilogue: normalize, write [B, L, H*D]
    float* ob = out + baseOff;
#pragma unroll
    for (int i = 0; i < 4; i++) {
        float inv = 1.f / l_i[i];
        int r = m0 + ty * 4 + i;
        float4 o = make_float4(acc[i][0] * inv, acc[i][1] * inv,
                               acc[i][2] * inv, acc[i][3] * inv);
        *(float4*)&ob[(size_t)r * EMB_C + tx * 4] = o;
    }
}

// ---------------------------------------------------------------------------
// launch
// ---------------------------------------------------------------------------
extern "C" void kernel_launch(void* const* d_in, const int* in_sizes, int n_in,
                              void* d_out, int out_size) {
    const float* Q  = (const float*)d_in[0];
    const float* K  = (const float*)d_in[1];
    const float* V  = (const float*)d_in[2];
    const float* WQ = (const float*)d_in[3];
    const float* bQ = (const float*)d_in[4];
    const float* WK = (const float*)d_in[5];
    const float* bK = (const float*)d_in[6];
    const float* WV = (const float*)d_in[7];
    const float* bV = (const float*)d_in[8];
    const float* WO = (const float*)d_in[9];
    const float* bO = (const float*)d_in[10];
    float* out = (float*)d_out;

    void *pq, *pk, *pv, *pa;
    cudaGetSymbolAddress(&pq, g_q);
    cudaGetSymbolAddress(&pk, g_k);
    cudaGetSymbolAddress(&pv, g_v);
    cudaGetSymbolAddress(&pa, g_att);

    dim3 gg(EMB_C / 128, MROWS / 128);  // (8, 64)
    gemm_bias_kernel<<<gg, 256>>>(Q, WQ, bQ, (float*)pq, MROWS, EMB_C, EMB_C);
    gemm_bias_kernel<<<gg, 256>>>(K, WK, bK, (float*)pk, MROWS, EMB_C, EMB_C);
    gemm_bias_kernel<<<gg, 256>>>(V, WV, bV, (float*)pv, MROWS, EMB_C, EMB_C);

    const int attn_smem = 4 * 64 * 68 * sizeof(float);  // 69632 B
    cudaFuncSetAttribute(attn_kernel, cudaFuncAttributeMaxDynamicSharedMemorySize,
                         attn_smem);
    dim3 ga(L_C / 64, HEADS_C, B_C);  // (32, 16, 4)
    attn_kernel<<<ga, 256, attn_smem>>>((const float*)pq, (const float*)pk,
                                        (const float*)pv, (float*)pa);

    gemm_bias_kernel<<<gg, 256>>>((const float*)pa, WO, bO, out, MROWS, EMB_C, EMB_C);
}

// round 3
// speedup vs baseline: 1.3831x; 1.3831x over previous
#include <cuda_runtime.h>
#include <cuda_bf16.h>
#include <math.h>
#include <cstdint>

// Problem constants (fixed by dataset)
#define B_C   4
#define L_C   2048
#define EMB_C 1024
#define HEADS_C 16
#define DH    64
#define MROWS (B_C * L_C)          // 8192
#define SCALE_C 0.125f             // 1/sqrt(64)

// ---------------------------------------------------------------------------
// Scratch (allocation-free rule: __device__ globals)
// ---------------------------------------------------------------------------
__device__ float g_q[MROWS * EMB_C];
__device__ float g_k[MROWS * EMB_C];
__device__ float g_v[MROWS * EMB_C];
__device__ float g_att[MROWS * EMB_C];
__device__ __nv_bfloat16 g_ihi[MROWS * EMB_C];   // split input (hi)
__device__ __nv_bfloat16 g_ilo[MROWS * EMB_C];   // split input (lo)
__device__ __nv_bfloat16 g_wthi[EMB_C * EMB_C];  // W^T split (hi)  [N,K]
__device__ __nv_bfloat16 g_wtlo[EMB_C * EMB_C];  // W^T split (lo)  [N,K]

// ---------------------------------------------------------------------------
// Warp-MMA helpers (arch-portable PTX: ldmatrix + mma.sync m16n8k16 bf16)
// ---------------------------------------------------------------------------
__device__ __forceinline__ uint32_t smem_u32(const void* p) {
    uint32_t a;
    asm("{ .reg .u64 t; cvta.to.shared.u64 t, %1; cvt.u32.u64 %0, t; }"
        : "=r"(a) : "l"(p));
    return a;
}
__device__ __forceinline__ void ldsm4(uint32_t* r, uint32_t addr) {
    asm volatile("ldmatrix.sync.aligned.m8n8.x4.shared.b16 {%0,%1,%2,%3}, [%4];"
                 : "=r"(r[0]), "=r"(r[1]), "=r"(r[2]), "=r"(r[3]) : "r"(addr));
}
__device__ __forceinline__ void mma16816(float* c, const uint32_t* a, const uint32_t* b) {
    asm volatile(
        "mma.sync.aligned.m16n8k16.row.col.f32.bf16.bf16.f32 "
        "{%0,%1,%2,%3}, {%4,%5,%6,%7}, {%8,%9}, {%0,%1,%2,%3};"
        : "+f"(c[0]), "+f"(c[1]), "+f"(c[2]), "+f"(c[3])
        : "r"(a[0]), "r"(a[1]), "r"(a[2]), "r"(a[3]), "r"(b[0]), "r"(b[1]));
}

// ---------------------------------------------------------------------------
// split kernel: fp32 -> (hi, lo) bf16
// ---------------------------------------------------------------------------
__global__ __launch_bounds__(256)
void split_kernel(const float* __restrict__ x, __nv_bfloat16* __restrict__ hi,
                  __nv_bfloat16* __restrict__ lo, int n) {
    int i = (blockIdx.x * 256 + threadIdx.x) * 4;
    if (i >= n) return;
    float4 v = *(const float4*)(x + i);
    __nv_bfloat16 h0 = __float2bfloat16(v.x), h1 = __float2bfloat16(v.y);
    __nv_bfloat16 h2 = __float2bfloat16(v.z), h3 = __float2bfloat16(v.w);
    __nv_bfloat16 l0 = __float2bfloat16(v.x - __bfloat162float(h0));
    __nv_bfloat16 l1 = __float2bfloat16(v.y - __bfloat162float(h1));
    __nv_bfloat16 l2 = __float2bfloat16(v.z - __bfloat162float(h2));
    __nv_bfloat16 l3 = __float2bfloat16(v.w - __bfloat162float(h3));
    *(__nv_bfloat162*)(hi + i)     = __nv_bfloat162(h0, h1);
    *(__nv_bfloat162*)(hi + i + 2) = __nv_bfloat162(h2, h3);
    *(__nv_bfloat162*)(lo + i)     = __nv_bfloat162(l0, l1);
    *(__nv_bfloat162*)(lo + i + 2) = __nv_bfloat162(l2, l3);
}

// ---------------------------------------------------------------------------
// weight transpose + split: W[K,N] fp32 -> Wt hi/lo [N,K] bf16
// ---------------------------------------------------------------------------
__global__ __launch_bounds__(256)
void wsplit_kernel(const float* __restrict__ W, __nv_bfloat16* __restrict__ hi,
                   __nv_bfloat16* __restrict__ lo) {
    __shared__ float t[32][33];
    int tx = threadIdx.x, ty = threadIdx.y;           // 32 x 8
    int n0 = blockIdx.x * 32, k0 = blockIdx.y * 32;
#pragma unroll
    for (int r = ty; r < 32; r += 8)
        t[r][tx] = W[(size_t)(k0 + r) * EMB_C + n0 + tx];
    __syncthreads();
#pragma unroll
    for (int r = ty; r < 32; r += 8) {
        float v = t[tx][r];                           // W[k0+tx][n0+r]
        __nv_bfloat16 h = __float2bfloat16(v);
        size_t o = (size_t)(n0 + r) * EMB_C + k0 + tx;
        hi[o] = h;
        lo[o] = __float2bfloat16(v - __bfloat162float(h));
    }
}

// ---------------------------------------------------------------------------
// mma.sync GEMM: C[M,N] = (Ahi+Alo)[M,K] @ (Bhi+Blo)^T[N,K] + bias
// CTA tile 128x128, BK=32, 8 warps (warp tile 64x32), hi/lo 3-product split.
// Smem rows padded to 40 bf16 (80B) -> ldmatrix phases conflict-free.
// ---------------------------------------------------------------------------
#define LDS_T 40

__global__ __launch_bounds__(256)
void gemm_tc_kernel(const __nv_bfloat16* __restrict__ Ahi,
                    const __nv_bfloat16* __restrict__ Alo,
                    const __nv_bfloat16* __restrict__ Bhi,
                    const __nv_bfloat16* __restrict__ Blo,
                    const float* __restrict__ bias, float* __restrict__ C,
                    int M, int N, int K) {
    __shared__ __nv_bfloat16 sA[2][128 * LDS_T];
    __shared__ __nv_bfloat16 sB[2][128 * LDS_T];

    const int tid = threadIdx.x;
    const int lane = tid & 31;
    const int wid = tid >> 5;
    const int warp_m = wid & 1;    // 0..1 -> 64 rows each
    const int warp_n = wid >> 1;   // 0..3 -> 32 cols each
    const int m0 = blockIdx.y * 128;
    const int n0 = blockIdx.x * 128;

    float acc[4][4][4];
#pragma unroll
    for (int mi = 0; mi < 4; mi++)
#pragma unroll
        for (int ni = 0; ni < 4; ni++)
#pragma unroll
            for (int r = 0; r < 4; r++) acc[mi][ni][r] = 0.f;

    // precomputed ldmatrix smem byte offsets (element offsets *2)
    const int a_row = (lane & 15);
    const int a_co  = (lane >> 4) << 3;
    const int b_rsel = (lane >> 4);          // 0/1 -> ntile pair
    const int b_row  = (lane & 7);
    const int b_co   = ((lane >> 3) & 1) << 3;

    for (int k0 = 0; k0 < K; k0 += 32) {
        // ---- global -> smem (4 tiles of 128x32) ----
#pragma unroll
        for (int i = tid; i < 512; i += 256) {
            int row = i >> 2, kc = (i & 3) << 3;
            size_t go = (size_t)(m0 + row) * K + k0 + kc;
            *(uint4*)(&sA[0][row * LDS_T + kc]) = *(const uint4*)(Ahi + go);
            *(uint4*)(&sA[1][row * LDS_T + kc]) = *(const uint4*)(Alo + go);
            size_t gob = (size_t)(n0 + row) * K + k0 + kc;
            *(uint4*)(&sB[0][row * LDS_T + kc]) = *(const uint4*)(Bhi + gob);
            *(uint4*)(&sB[1][row * LDS_T + kc]) = *(const uint4*)(Blo + gob);
        }
        __syncthreads();

#pragma unroll
        for (int ks = 0; ks < 2; ks++) {
            // B fragments: [split][ntile][2]
            uint32_t bf[2][4][2];
#pragma unroll
            for (int s = 0; s < 2; s++)
#pragma unroll
                for (int np = 0; np < 2; np++) {   // ntile pairs (0,1),(2,3)
                    int rowe = (warp_n * 32 + (np * 2 + b_rsel) * 8 + b_row) * LDS_T
                               + ks * 16 + b_co;
                    uint32_t addr = smem_u32(&sB[s][0]) + rowe * 2;
                    uint32_t r4[4];
                    ldsm4(r4, addr);
                    bf[s][np * 2 + 0][0] = r4[0];
                    bf[s][np * 2 + 0][1] = r4[1];
                    bf[s][np * 2 + 1][0] = r4[2];
                    bf[s][np * 2 + 1][1] = r4[3];
                }
#pragma unroll
            for (int mi = 0; mi < 4; mi++) {
                uint32_t af[2][4];
#pragma unroll
                for (int s = 0; s < 2; s++) {
                    int rowe = (warp_m * 64 + mi * 16 + a_row) * LDS_T + ks * 16 + a_co;
                    ldsm4(af[s], smem_u32(&sA[s][0]) + rowe * 2);
                }
#pragma unroll
                for (int ni = 0; ni < 4; ni++) {
                    mma16816(acc[mi][ni], af[0], bf[0][ni]);  // hi*hi
                    mma16816(acc[mi][ni], af[0], bf[1][ni]);  // hi*lo
                    mma16816(acc[mi][ni], af[1], bf[0][ni]);  // lo*hi
                }
            }
        }
        __syncthreads();
    }

    // ---- epilogue: add bias, write fp32 ----
#pragma unroll
    for (int mi = 0; mi < 4; mi++) {
#pragma unroll
        for (int ni = 0; ni < 4; ni++) {
            int col = n0 + warp_n * 32 + ni * 8 + (lane & 3) * 2;
            float2 bv = *(const float2*)&bias[col];
            int r0 = m0 + warp_m * 64 + mi * 16 + (lane >> 2);
            float2 o0 = make_float2(acc[mi][ni][0] + bv.x, acc[mi][ni][1] + bv.y);
            float2 o1 = make_float2(acc[mi][ni][2] + bv.x, acc[mi][ni][3] + bv.y);
            *(float2*)&C[(size_t)r0 * N + col] = o0;
            *(float2*)&C[(size_t)(r0 + 8) * N + col] = o1;
        }
    }
}

// ---------------------------------------------------------------------------
// Flash attention (causal), fp32. BM=BN=64, D=64, 256 threads.  (unchanged)
// ---------------------------------------------------------------------------
__global__ __launch_bounds__(256)
void attn_kernel(const float* __restrict__ q, const float* __restrict__ k,
                 const float* __restrict__ v, float* __restrict__ out) {
    extern __shared__ float smemf[];
    float* sQ = smemf;
    float* sK = smemf + 64 * 68;
    float* sV = smemf + 2 * 64 * 68;
    float* sP = smemf + 3 * 64 * 68;

    const int tid = threadIdx.x;
    const int m0 = blockIdx.x * 64;
    const int h  = blockIdx.y;
    const int b  = blockIdx.z;
    const int tx = tid & 15;
    const int ty = tid >> 4;

    const size_t baseOff = (size_t)b * L_C * EMB_C + (size_t)h * DH;
    const float* qb = q + baseOff;
    const float* kb = k + baseOff;
    const float* vb = v + baseOff;

    {
        int r   = tid & 63;
        int kk0 = (tid >> 6) << 4;
        const float* src = qb + (size_t)(m0 + r) * EMB_C;
#pragma unroll
        for (int c = 0; c < 4; c++) {
            float4 g = *(const float4*)&src[kk0 + c * 4];
            sQ[(kk0 + c * 4 + 0) * 68 + r] = g.x * SCALE_C;
            sQ[(kk0 + c * 4 + 1) * 68 + r] = g.y * SCALE_C;
            sQ[(kk0 + c * 4 + 2) * 68 + r] = g.z * SCALE_C;
            sQ[(kk0 + c * 4 + 3) * 68 + r] = g.w * SCALE_C;
        }
    }

    float m_i[4], l_i[4], acc[4][4];
#pragma unroll
    for (int i = 0; i < 4; i++) {
        m_i[i] = -INFINITY;
        l_i[i] = 0.f;
#pragma unroll
        for (int j = 0; j < 4; j++) acc[i][j] = 0.f;
    }

    for (int n0 = 0; n0 <= m0; n0 += 64) {
        __syncthreads();
        {
            int r   = tid & 63;
            int kk0 = (tid >> 6) << 4;
            const float* src = kb + (size_t)(n0 + r) * EMB_C;
#pragma unroll
            for (int c = 0; c < 4; c++) {
                float4 g = *(const float4*)&src[kk0 + c * 4];
                sK[(kk0 + c * 4 + 0) * 68 + r] = g.x;
                sK[(kk0 + c * 4 + 1) * 68 + r] = g.y;
                sK[(kk0 + c * 4 + 2) * 68 + r] = g.z;
                sK[(kk0 + c * 4 + 3) * 68 + r] = g.w;
            }
        }
        {
            int row = tid >> 2;
            int c0  = (tid & 3) << 4;
            const float* src = vb + (size_t)(n0 + row) * EMB_C;
#pragma unroll
            for (int j4 = 0; j4 < 4; j4++) {
                float4 g = *(const float4*)&src[c0 + j4 * 4];
                *(float4*)&sV[row * 68 + c0 + j4 * 4] = g;
            }
        }
        __syncthreads();

        float s[4][4];
#pragma unroll
        for (int i = 0; i < 4; i++)
#pragma unroll
            for (int j = 0; j < 4; j++) s[i][j] = 0.f;
#pragma unroll
        for (int kk = 0; kk < 64; kk++) {
            float4 qf = *(float4*)&sQ[kk * 68 + ty * 4];
            float4 kf = *(float4*)&sK[kk * 68 + tx * 4];
            float a[4] = {qf.x, qf.y, qf.z, qf.w};
            float c[4] = {kf.x, kf.y, kf.z, kf.w};
#pragma unroll
            for (int i = 0; i < 4; i++)
#pragma unroll
                for (int j = 0; j < 4; j++) s[i][j] = fmaf(a[i], c[j], s[i][j]);
        }

        if (n0 == m0) {
#pragma unroll
            for (int i = 0; i < 4; i++)
#pragma unroll
                for (int j = 0; j < 4; j++)
                    if (tx * 4 + j > ty * 4 + i) s[i][j] = -INFINITY;
        }

#pragma unroll
        for (int i = 0; i < 4; i++) {
            float tm = fmaxf(fmaxf(s[i][0], s[i][1]), fmaxf(s[i][2], s[i][3]));
#pragma unroll
            for (int off = 8; off > 0; off >>= 1)
                tm = fmaxf(tm, __shfl_xor_sync(0xffffffffu, tm, off));
            float mn = fmaxf(m_i[i], tm);
            float f  = __expf(m_i[i] - mn);
            float rs = 0.f;
#pragma unroll
            for (int j = 0; j < 4; j++) {
                s[i][j] = __expf(s[i][j] - mn);
                rs += s[i][j];
            }
#pragma unroll
            for (int off = 8; off > 0; off >>= 1)
                rs += __shfl_xor_sync(0xffffffffu, rs, off);
            l_i[i] = l_i[i] * f + rs;
            m_i[i] = mn;
#pragma unroll
            for (int j = 0; j < 4; j++) acc[i][j] *= f;
        }

#pragma unroll
        for (int i = 0; i < 4; i++)
            *(float4*)&sP[(ty * 4 + i) * 68 + tx * 4] =
                make_float4(s[i][0], s[i][1], s[i][2], s[i][3]);
        __syncthreads();

#pragma unroll 8
        for (int col = 0; col < 64; col++) {
            float4 vv = *(float4*)&sV[col * 68 + tx * 4];
#pragma unroll
            for (int i = 0; i < 4; i++) {
                float pr = sP[(ty * 4 + i) * 68 + col];
                acc[i][0] = fmaf(pr, vv.x, acc[i][0]);
                acc[i][1] = fmaf(pr, vv.y, acc[i][1]);
                acc[i][2] = fmaf(pr, vv.z, acc[i][2]);
                acc[i][3] = fmaf(pr, vv.w, acc[i][3]);
            }
        }
    }

    float* ob = out + baseOff;
#pragma unroll
    for (int i = 0; i < 4; i++) {
        float inv = 1.f / l_i[i];
        int r = m0 + ty * 4 + i;
        float4 o = make_float4(acc[i][0] * inv, acc[i][1] * inv,
                               acc[i][2] * inv, acc[i][3] * inv);
        *(float4*)&ob[(size_t)r * EMB_C + tx * 4] = o;
    }
}

// ---------------------------------------------------------------------------
// launch
// ---------------------------------------------------------------------------
extern "C" void kernel_launch(void* const* d_in, const int* in_sizes, int n_in,
                              void* d_out, int out_size) {
    const float* Q  = (const float*)d_in[0];
    const float* K  = (const float*)d_in[1];
    const float* V  = (const float*)d_in[2];
    const float* WQ = (const float*)d_in[3];
    const float* bQ = (const float*)d_in[4];
    const float* WK = (const float*)d_in[5];
    const float* bK = (const float*)d_in[6];
    const float* WV = (const float*)d_in[7];
    const float* bV = (const float*)d_in[8];
    const float* WO = (const float*)d_in[9];
    const float* bO = (const float*)d_in[10];
    float* out = (float*)d_out;

    void *pq, *pk, *pv, *pa, *pih, *pil, *pwh, *pwl;
    cudaGetSymbolAddress(&pq, g_q);
    cudaGetSymbolAddress(&pk, g_k);
    cudaGetSymbolAddress(&pv, g_v);
    cudaGetSymbolAddress(&pa, g_att);
    cudaGetSymbolAddress(&pih, g_ihi);
    cudaGetSymbolAddress(&pil, g_ilo);
    cudaGetSymbolAddress(&pwh, g_wthi);
    cudaGetSymbolAddress(&pwl, g_wtlo);
    __nv_bfloat16* ihi = (__nv_bfloat16*)pih;
    __nv_bfloat16* ilo = (__nv_bfloat16*)pil;
    __nv_bfloat16* whi = (__nv_bfloat16*)pwh;
    __nv_bfloat16* wlo = (__nv_bfloat16*)pwl;

    const int NELEM = MROWS * EMB_C;
    dim3 gsplit(NELEM / 1024);
    dim3 gw(EMB_C / 32, EMB_C / 32), bw(32, 8);
    dim3 gg(EMB_C / 128, MROWS / 128);  // (8, 64)

    // Q projection
    split_kernel<<<gsplit, 256>>>(Q, ihi, ilo, NELEM);
    wsplit_kernel<<<gw, bw>>>(WQ, whi, wlo);
    gemm_tc_kernel<<<gg, 256>>>(ihi, ilo, whi, wlo, bQ, (float*)pq,
                                MROWS, EMB_C, EMB_C);
    // K projection
    split_kernel<<<gsplit, 256>>>(K, ihi, ilo, NELEM);
    wsplit_kernel<<<gw, bw>>>(WK, whi, wlo);
    gemm_tc_kernel<<<gg, 256>>>(ihi, ilo, whi, wlo, bK, (float*)pk,
                                MROWS, EMB_C, EMB_C);
    // V projection
    split_kernel<<<gsplit, 256>>>(V, ihi, ilo, NELEM);
    wsplit_kernel<<<gw, bw>>>(WV, whi, wlo);
    gemm_tc_kernel<<<gg, 256>>>(ihi, ilo, whi, wlo, bV, (float*)pv,
                                MROWS, EMB_C, EMB_C);

    // attention
    const int attn_smem = 4 * 64 * 68 * sizeof(float);  // 69632 B
    cudaFuncSetAttribute(attn_kernel, cudaFuncAttributeMaxDynamicSharedMemorySize,
                         attn_smem);
    dim3 ga(L_C / 64, HEADS_C, B_C);
    attn_kernel<<<ga, 256, attn_smem>>>((const float*)pq, (const float*)pk,
                                        (const float*)pv, (float*)pa);

    // O projection
    split_kernel<<<gsplit, 256>>>((const float*)pa, ihi, ilo, NELEM);
    wsplit_kernel<<<gw, bw>>>(WO, whi, wlo);
    gemm_tc_kernel<<<gg, 256>>>(ihi, ilo, whi, wlo, bO, out,
                                MROWS, EMB_C, EMB_C);
}

// round 4
// speedup vs baseline: 2.1993x; 1.5901x over previous
#include <cuda_runtime.h>
#include <cuda_bf16.h>
#include <math.h>
#include <cstdint>

// Problem constants (fixed by dataset)
#define B_C   4
#define L_C   2048
#define EMB_C 1024
#define HEADS_C 16
#define DH    64
#define MROWS (B_C * L_C)          // 8192
#define SCALE_C 0.125f             // 1/sqrt(64)

// ---------------------------------------------------------------------------
// Scratch (allocation-free rule: __device__ globals)
// ---------------------------------------------------------------------------
__device__ float g_q[MROWS * EMB_C];
__device__ float g_k[MROWS * EMB_C];
__device__ float g_v[MROWS * EMB_C];
__device__ float g_att[MROWS * EMB_C];
__device__ __nv_bfloat16 g_ihi[MROWS * EMB_C];   // split input (hi)
__device__ __nv_bfloat16 g_ilo[MROWS * EMB_C];   // split input (lo)
__device__ __nv_bfloat16 g_wthi[EMB_C * EMB_C];  // W^T split (hi)  [N,K]
__device__ __nv_bfloat16 g_wtlo[EMB_C * EMB_C];  // W^T split (lo)  [N,K]

// ---------------------------------------------------------------------------
// Warp-MMA helpers (arch-portable PTX: ldmatrix + mma.sync m16n8k16 bf16)
// ---------------------------------------------------------------------------
__device__ __forceinline__ uint32_t smem_u32(const void* p) {
    uint32_t a;
    asm("{ .reg .u64 t; cvta.to.shared.u64 t, %1; cvt.u32.u64 %0, t; }"
        : "=r"(a) : "l"(p));
    return a;
}
__device__ __forceinline__ void ldsm4(uint32_t* r, uint32_t addr) {
    asm volatile("ldmatrix.sync.aligned.m8n8.x4.shared.b16 {%0,%1,%2,%3}, [%4];"
                 : "=r"(r[0]), "=r"(r[1]), "=r"(r[2]), "=r"(r[3]) : "r"(addr));
}
__device__ __forceinline__ void ldsm4t(uint32_t* r, uint32_t addr) {
    asm volatile("ldmatrix.sync.aligned.m8n8.x4.trans.shared.b16 {%0,%1,%2,%3}, [%4];"
                 : "=r"(r[0]), "=r"(r[1]), "=r"(r[2]), "=r"(r[3]) : "r"(addr));
}
__device__ __forceinline__ void mma16816(float* c, const uint32_t* a, const uint32_t* b) {
    asm volatile(
        "mma.sync.aligned.m16n8k16.row.col.f32.bf16.bf16.f32 "
        "{%0,%1,%2,%3}, {%4,%5,%6,%7}, {%8,%9}, {%0,%1,%2,%3};"
        : "+f"(c[0]), "+f"(c[1]), "+f"(c[2]), "+f"(c[3])
        : "r"(a[0]), "r"(a[1]), "r"(a[2]), "r"(a[3]), "r"(b[0]), "r"(b[1]));
}
// split two fp32 into packed bf16x2 hi and lo parts
__device__ __forceinline__ void split2(float a, float b, uint32_t& hp, uint32_t& lp) {
    __nv_bfloat16 ha = __float2bfloat16(a), hb = __float2bfloat16(b);
    __nv_bfloat16 la = __float2bfloat16(a - __bfloat162float(ha));
    __nv_bfloat16 lb = __float2bfloat16(b - __bfloat162float(hb));
    __nv_bfloat162 h2(ha, hb), l2(la, lb);
    hp = *(uint32_t*)&h2;
    lp = *(uint32_t*)&l2;
}

// ---------------------------------------------------------------------------
// split kernel: fp32 -> (hi, lo) bf16
// ---------------------------------------------------------------------------
__global__ __launch_bounds__(256)
void split_kernel(const float* __restrict__ x, __nv_bfloat16* __restrict__ hi,
                  __nv_bfloat16* __restrict__ lo, int n) {
    int i = (blockIdx.x * 256 + threadIdx.x) * 4;
    if (i >= n) return;
    float4 v = *(const float4*)(x + i);
    uint32_t hp0, lp0, hp1, lp1;
    split2(v.x, v.y, hp0, lp0);
    split2(v.z, v.w, hp1, lp1);
    *(uint2*)(hi + i) = make_uint2(hp0, hp1);
    *(uint2*)(lo + i) = make_uint2(lp0, lp1);
}

// ---------------------------------------------------------------------------
// weight transpose + split: W[K,N] fp32 -> Wt hi/lo [N,K] bf16
// ---------------------------------------------------------------------------
__global__ __launch_bounds__(256)
void wsplit_kernel(const float* __restrict__ W, __nv_bfloat16* __restrict__ hi,
                   __nv_bfloat16* __restrict__ lo) {
    __shared__ float t[32][33];
    int tx = threadIdx.x, ty = threadIdx.y;           // 32 x 8
    int n0 = blockIdx.x * 32, k0 = blockIdx.y * 32;
#pragma unroll
    for (int r = ty; r < 32; r += 8)
        t[r][tx] = W[(size_t)(k0 + r) * EMB_C + n0 + tx];
    __syncthreads();
#pragma unroll
    for (int r = ty; r < 32; r += 8) {
        float v = t[tx][r];                           // W[k0+tx][n0+r]
        __nv_bfloat16 h = __float2bfloat16(v);
        size_t o = (size_t)(n0 + r) * EMB_C + k0 + tx;
        hi[o] = h;
        lo[o] = __float2bfloat16(v - __bfloat162float(h));
    }
}

// ---------------------------------------------------------------------------
// mma.sync GEMM: C[M,N] = (Ahi+Alo)[M,K] @ (Bhi+Blo)^T[N,K] + bias
// CTA tile 128x128, BK=32, 8 warps (warp tile 64x32), hi/lo 3-product split.
// ---------------------------------------------------------------------------
#define LDS_T 40

__global__ __launch_bounds__(256)
void gemm_tc_kernel(const __nv_bfloat16* __restrict__ Ahi,
                    const __nv_bfloat16* __restrict__ Alo,
                    const __nv_bfloat16* __restrict__ Bhi,
                    const __nv_bfloat16* __restrict__ Blo,
                    const float* __restrict__ bias, float* __restrict__ C,
                    int M, int N, int K) {
    __shared__ __nv_bfloat16 sA[2][128 * LDS_T];
    __shared__ __nv_bfloat16 sB[2][128 * LDS_T];

    const int tid = threadIdx.x;
    const int lane = tid & 31;
    const int wid = tid >> 5;
    const int warp_m = wid & 1;    // 0..1 -> 64 rows each
    const int warp_n = wid >> 1;   // 0..3 -> 32 cols each
    const int m0 = blockIdx.y * 128;
    const int n0 = blockIdx.x * 128;

    float acc[4][4][4];
#pragma unroll
    for (int mi = 0; mi < 4; mi++)
#pragma unroll
        for (int ni = 0; ni < 4; ni++)
#pragma unroll
            for (int r = 0; r < 4; r++) acc[mi][ni][r] = 0.f;

    const int a_row = (lane & 15);
    const int a_co  = (lane >> 4) << 3;
    const int b_rsel = (lane >> 4);
    const int b_row  = (lane & 7);
    const int b_co   = ((lane >> 3) & 1) << 3;

    for (int k0 = 0; k0 < K; k0 += 32) {
#pragma unroll
        for (int i = tid; i < 512; i += 256) {
            int row = i >> 2, kc = (i & 3) << 3;
            size_t go = (size_t)(m0 + row) * K + k0 + kc;
            *(uint4*)(&sA[0][row * LDS_T + kc]) = *(const uint4*)(Ahi + go);
            *(uint4*)(&sA[1][row * LDS_T + kc]) = *(const uint4*)(Alo + go);
            size_t gob = (size_t)(n0 + row) * K + k0 + kc;
            *(uint4*)(&sB[0][row * LDS_T + kc]) = *(const uint4*)(Bhi + gob);
            *(uint4*)(&sB[1][row * LDS_T + kc]) = *(const uint4*)(Blo + gob);
        }
        __syncthreads();

#pragma unroll
        for (int ks = 0; ks < 2; ks++) {
            uint32_t bf[2][4][2];
#pragma unroll
            for (int s = 0; s < 2; s++)
#pragma unroll
                for (int np = 0; np < 2; np++) {
                    int rowe = (warp_n * 32 + (np * 2 + b_rsel) * 8 + b_row) * LDS_T
                               + ks * 16 + b_co;
                    uint32_t addr = smem_u32(&sB[s][0]) + rowe * 2;
                    uint32_t r4[4];
                    ldsm4(r4, addr);
                    bf[s][np * 2 + 0][0] = r4[0];
                    bf[s][np * 2 + 0][1] = r4[1];
                    bf[s][np * 2 + 1][0] = r4[2];
                    bf[s][np * 2 + 1][1] = r4[3];
                }
#pragma unroll
            for (int mi = 0; mi < 4; mi++) {
                uint32_t af[2][4];
#pragma unroll
                for (int s = 0; s < 2; s++) {
                    int rowe = (warp_m * 64 + mi * 16 + a_row) * LDS_T + ks * 16 + a_co;
                    ldsm4(af[s], smem_u32(&sA[s][0]) + rowe * 2);
                }
#pragma unroll
                for (int ni = 0; ni < 4; ni++) {
                    mma16816(acc[mi][ni], af[0], bf[0][ni]);  // hi*hi
                    mma16816(acc[mi][ni], af[0], bf[1][ni]);  // hi*lo
                    mma16816(acc[mi][ni], af[1], bf[0][ni]);  // lo*hi
                }
            }
        }
        __syncthreads();
    }

#pragma unroll
    for (int mi = 0; mi < 4; mi++) {
#pragma unroll
        for (int ni = 0; ni < 4; ni++) {
            int col = n0 + warp_n * 32 + ni * 8 + (lane & 3) * 2;
            float2 bv = *(const float2*)&bias[col];
            int r0 = m0 + warp_m * 64 + mi * 16 + (lane >> 2);
            float2 o0 = make_float2(acc[mi][ni][0] + bv.x, acc[mi][ni][1] + bv.y);
            float2 o1 = make_float2(acc[mi][ni][2] + bv.x, acc[mi][ni][3] + bv.y);
            *(float2*)&C[(size_t)r0 * N + col] = o0;
            *(float2*)&C[(size_t)(r0 + 8) * N + col] = o1;
        }
    }
}

// ---------------------------------------------------------------------------
// Tensor-core flash attention (causal). BM=128, BN=64, D=64, 8 warps.
// Q/K/V converted fp32 -> bf16 hi/lo in-kernel; 3-product MMA splits.
// smem rows padded to stride 72 bf16.
// ---------------------------------------------------------------------------
#define AT_LDS 72

__global__ __launch_bounds__(256)
void attn_tc_kernel(const float* __restrict__ q, const float* __restrict__ k,
                    const float* __restrict__ v, float* __restrict__ out) {
    __shared__ __align__(16) char sm[4 * 64 * AT_LDS * 2];   // 36864 B
    __nv_bfloat16* sKhi = (__nv_bfloat16*)sm;
    __nv_bfloat16* sKlo = sKhi + 64 * AT_LDS;
    __nv_bfloat16* sVhi = sKhi + 2 * 64 * AT_LDS;
    __nv_bfloat16* sVlo = sKhi + 3 * 64 * AT_LDS;
    // Q staging overlays K (hi) and V (lo) regions during prologue
    __nv_bfloat16* sQhi = sKhi;                     // 128*72 elems
    __nv_bfloat16* sQlo = sVhi;                     // 128*72 elems

    const int tid = threadIdx.x;
    const int lane = tid & 31;
    const int w = tid >> 5;                         // warp 0..7 -> 16 rows each
    const int quad = lane >> 2;                     // 0..7 (row within octet)
    const int par2 = (lane & 3) * 2;                // col pair within n8

    const int m0 = blockIdx.x * 128;
    const int h  = blockIdx.y;
    const int b  = blockIdx.z;
    const size_t baseOff = (size_t)b * L_C * EMB_C + (size_t)h * DH;
    const float* qb = q + baseOff;
    const float* kb = k + baseOff;
    const float* vb = v + baseOff;

    const uint32_t u_sKhi = smem_u32(sKhi);
    const uint32_t u_sKlo = smem_u32(sKlo);
    const uint32_t u_sVhi = smem_u32(sVhi);
    const uint32_t u_sVlo = smem_u32(sVlo);

    // ---- prologue: stage Q (scaled) as bf16 hi/lo, load fragments ----
    {
        int row = tid >> 1;                 // 0..127
        int d0 = (tid & 1) * 32;
        const float* src = qb + (size_t)(m0 + row) * EMB_C + d0;
#pragma unroll
        for (int j = 0; j < 8; j++) {
            float4 g = *(const float4*)(src + j * 4);
            uint32_t hp0, lp0, hp1, lp1;
            split2(g.x * SCALE_C, g.y * SCALE_C, hp0, lp0);
            split2(g.z * SCALE_C, g.w * SCALE_C, hp1, lp1);
            *(uint2*)&sQhi[row * AT_LDS + d0 + j * 4] = make_uint2(hp0, hp1);
            *(uint2*)&sQlo[row * AT_LDS + d0 + j * 4] = make_uint2(lp0, lp1);
        }
    }
    __syncthreads();

    uint32_t qfh[4][4], qfl[4][4];
    {
        int r = w * 16 + (lane & 15);
        int c = (lane >> 4) * 8;
#pragma unroll
        for (int kc = 0; kc < 4; kc++) {
            ldsm4(qfh[kc], smem_u32(sQhi) + (r * AT_LDS + kc * 16 + c) * 2);
            ldsm4(qfl[kc], smem_u32(sQlo) + (r * AT_LDS + kc * 16 + c) * 2);
        }
    }
    __syncthreads();   // done with Q staging region

    float oacc[8][4];
#pragma unroll
    for (int nt = 0; nt < 8; nt++)
#pragma unroll
        for (int r = 0; r < 4; r++) oacc[nt][r] = 0.f;
    float m_lo = -1e30f, m_hi = -1e30f, l_lo = 0.f, l_hi = 0.f;

    const int row_lo_g = m0 + w * 16 + quad;   // global row (lo half)
    const int warp_max_row = m0 + w * 16 + 15;

    for (int n0 = 0; n0 < m0 + 128; n0 += 64) {
        // ---- load + convert K,V tile ----
        {
            int row = tid >> 2;             // 0..63
            int d0 = (tid & 3) << 4;        // 0,16,32,48
            const float* ksrc = kb + (size_t)(n0 + row) * EMB_C + d0;
            const float* vsrc = vb + (size_t)(n0 + row) * EMB_C + d0;
#pragma unroll
            for (int j = 0; j < 4; j++) {
                float4 gk = *(const float4*)(ksrc + j * 4);
                uint32_t hp0, lp0, hp1, lp1;
                split2(gk.x, gk.y, hp0, lp0);
                split2(gk.z, gk.w, hp1, lp1);
                *(uint2*)&sKhi[row * AT_LDS + d0 + j * 4] = make_uint2(hp0, hp1);
                *(uint2*)&sKlo[row * AT_LDS + d0 + j * 4] = make_uint2(lp0, lp1);
                float4 gv = *(const float4*)(vsrc + j * 4);
                split2(gv.x, gv.y, hp0, lp0);
                split2(gv.z, gv.w, hp1, lp1);
                *(uint2*)&sVhi[row * AT_LDS + d0 + j * 4] = make_uint2(hp0, hp1);
                *(uint2*)&sVlo[row * AT_LDS + d0 + j * 4] = make_uint2(lp0, lp1);
            }
        }
        __syncthreads();

        if (n0 <= warp_max_row) {
            // ---- S = Q K^T ----
            float sacc[8][4];
#pragma unroll
            for (int nt = 0; nt < 8; nt++)
#pragma unroll
                for (int r = 0; r < 4; r++) sacc[nt][r] = 0.f;

            const int kb_row = ((lane >> 4) & 1) * 8 + (lane & 7);
            const int kb_col = ((lane >> 3) & 1) * 8;
#pragma unroll
            for (int kc = 0; kc < 4; kc++) {
                uint32_t kh[8][2], kl[8][2];
#pragma unroll
                for (int np = 0; np < 4; np++) {
                    uint32_t t4[4];
                    uint32_t off = ((np * 16 + kb_row) * AT_LDS + kc * 16 + kb_col) * 2;
                    ldsm4(t4, u_sKhi + off);
                    kh[np * 2 + 0][0] = t4[0]; kh[np * 2 + 0][1] = t4[1];
                    kh[np * 2 + 1][0] = t4[2]; kh[np * 2 + 1][1] = t4[3];
                    ldsm4(t4, u_sKlo + off);
                    kl[np * 2 + 0][0] = t4[0]; kl[np * 2 + 0][1] = t4[1];
                    kl[np * 2 + 1][0] = t4[2]; kl[np * 2 + 1][1] = t4[3];
                }
#pragma unroll
                for (int nt = 0; nt < 8; nt++) {
                    mma16816(sacc[nt], qfh[kc], kh[nt]);
                    mma16816(sacc[nt], qfh[kc], kl[nt]);
                    mma16816(sacc[nt], qfl[kc], kh[nt]);
                }
            }

            // ---- causal mask (partial tiles only) ----
            if (n0 + 63 > row_lo_g) {   // some element of lo rows may be masked
#pragma unroll
                for (int nt = 0; nt < 8; nt++) {
#pragma unroll
                    for (int c = 0; c < 2; c++) {
                        int col = n0 + nt * 8 + par2 + c;
                        if (col > row_lo_g) sacc[nt][c] = -1e30f;
                        if (col > row_lo_g + 8) sacc[nt][2 + c] = -1e30f;
                    }
                }
            } else if (n0 + 63 > row_lo_g + 8) {
#pragma unroll
                for (int nt = 0; nt < 8; nt++)
#pragma unroll
                    for (int c = 0; c < 2; c++) {
                        int col = n0 + nt * 8 + par2 + c;
                        if (col > row_lo_g + 8) sacc[nt][2 + c] = -1e30f;
                    }
            }

            // ---- online softmax (two rows per thread) ----
            {
                float mx0 = -1e30f, mx1 = -1e30f;
#pragma unroll
                for (int nt = 0; nt < 8; nt++) {
                    mx0 = fmaxf(mx0, fmaxf(sacc[nt][0], sacc[nt][1]));
                    mx1 = fmaxf(mx1, fmaxf(sacc[nt][2], sacc[nt][3]));
                }
                mx0 = fmaxf(mx0, __shfl_xor_sync(0xffffffffu, mx0, 1));
                mx0 = fmaxf(mx0, __shfl_xor_sync(0xffffffffu, mx0, 2));
                mx1 = fmaxf(mx1, __shfl_xor_sync(0xffffffffu, mx1, 1));
                mx1 = fmaxf(mx1, __shfl_xor_sync(0xffffffffu, mx1, 2));
                float mn0 = fmaxf(m_lo, mx0), mn1 = fmaxf(m_hi, mx1);
                float f0 = __expf(m_lo - mn0), f1 = __expf(m_hi - mn1);
                float rs0 = 0.f, rs1 = 0.f;
#pragma unroll
                for (int nt = 0; nt < 8; nt++) {
                    sacc[nt][0] = __expf(sacc[nt][0] - mn0);
                    sacc[nt][1] = __expf(sacc[nt][1] - mn0);
                    sacc[nt][2] = __expf(sacc[nt][2] - mn1);
                    sacc[nt][3] = __expf(sacc[nt][3] - mn1);
                    rs0 += sacc[nt][0] + sacc[nt][1];
                    rs1 += sacc[nt][2] + sacc[nt][3];
                }
                rs0 += __shfl_xor_sync(0xffffffffu, rs0, 1);
                rs0 += __shfl_xor_sync(0xffffffffu, rs0, 2);
                rs1 += __shfl_xor_sync(0xffffffffu, rs1, 1);
                rs1 += __shfl_xor_sync(0xffffffffu, rs1, 2);
                l_lo = l_lo * f0 + rs0;
                l_hi = l_hi * f1 + rs1;
                m_lo = mn0;
                m_hi = mn1;
#pragma unroll
                for (int nt = 0; nt < 8; nt++) {
                    oacc[nt][0] *= f0;
                    oacc[nt][1] *= f0;
                    oacc[nt][2] *= f1;
                    oacc[nt][3] *= f1;
                }
            }

            // ---- PV: P (hi/lo from regs) x V (hi/lo from smem) ----
            const int vb_row = ((lane >> 3) & 1) * 8 + (lane & 7);
            const int vb_col = ((lane >> 4) & 1) * 8;
#pragma unroll
            for (int ks = 0; ks < 4; ks++) {
                uint32_t pah[4], pal[4];
                split2(sacc[2 * ks][0], sacc[2 * ks][1], pah[0], pal[0]);
                split2(sacc[2 * ks][2], sacc[2 * ks][3], pah[1], pal[1]);
                split2(sacc[2 * ks + 1][0], sacc[2 * ks + 1][1], pah[2], pal[2]);
                split2(sacc[2 * ks + 1][2], sacc[2 * ks + 1][3], pah[3], pal[3]);

                uint32_t vh[8][2], vl[8][2];
#pragma unroll
                for (int dp = 0; dp < 4; dp++) {
                    uint32_t t4[4];
                    uint32_t off = ((ks * 16 + vb_row) * AT_LDS + dp * 16 + vb_col) * 2;
                    ldsm4t(t4, u_sVhi + off);
                    vh[dp * 2 + 0][0] = t4[0]; vh[dp * 2 + 0][1] = t4[1];
                    vh[dp * 2 + 1][0] = t4[2]; vh[dp * 2 + 1][1] = t4[3];
                    ldsm4t(t4, u_sVlo + off);
                    vl[dp * 2 + 0][0] = t4[0]; vl[dp * 2 + 0][1] = t4[1];
                    vl[dp * 2 + 1][0] = t4[2]; vl[dp * 2 + 1][1] = t4[3];
                }
#pragma unroll
                for (int nt = 0; nt < 8; nt++) {
                    mma16816(oacc[nt], pah, vh[nt]);
                    mma16816(oacc[nt], pah, vl[nt]);
                    mma16816(oacc[nt], pal, vh[nt]);
                }
            }
        }
        __syncthreads();   // all reads done before next tile overwrite
    }

    // ---- epilogue ----
    float inv0 = 1.f / l_lo, inv1 = 1.f / l_hi;
    float* ob = out + baseOff;
    const int r0 = m0 + w * 16 + quad;
#pragma unroll
    for (int nt = 0; nt < 8; nt++) {
        int col = nt * 8 + par2;
        *(float2*)&ob[(size_t)r0 * EMB_C + col] =
            make_float2(oacc[nt][0] * inv0, oacc[nt][1] * inv0);
        *(float2*)&ob[(size_t)(r0 + 8) * EMB_C + col] =
            make_float2(oacc[nt][2] * inv1, oacc[nt][3] * inv1);
    }
}

// ---------------------------------------------------------------------------
// launch
// ---------------------------------------------------------------------------
extern "C" void kernel_launch(void* const* d_in, const int* in_sizes, int n_in,
                              void* d_out, int out_size) {
    const float* Q  = (const float*)d_in[0];
    const float* K  = (const float*)d_in[1];
    const float* V  = (const float*)d_in[2];
    const float* WQ = (const float*)d_in[3];
    const float* bQ = (const float*)d_in[4];
    const float* WK = (const float*)d_in[5];
    const float* bK = (const float*)d_in[6];
    const float* WV = (const float*)d_in[7];
    const float* bV = (const float*)d_in[8];
    const float* WO = (const float*)d_in[9];
    const float* bO = (const float*)d_in[10];
    float* out = (float*)d_out;

    void *pq, *pk, *pv, *pa, *pih, *pil, *pwh, *pwl;
    cudaGetSymbolAddress(&pq, g_q);
    cudaGetSymbolAddress(&pk, g_k);
    cudaGetSymbolAddress(&pv, g_v);
    cudaGetSymbolAddress(&pa, g_att);
    cudaGetSymbolAddress(&pih, g_ihi);
    cudaGetSymbolAddress(&pil, g_ilo);
    cudaGetSymbolAddress(&pwh, g_wthi);
    cudaGetSymbolAddress(&pwl, g_wtlo);
    __nv_bfloat16* ihi = (__nv_bfloat16*)pih;
    __nv_bfloat16* ilo = (__nv_bfloat16*)pil;
    __nv_bfloat16* whi = (__nv_bfloat16*)pwh;
    __nv_bfloat16* wlo = (__nv_bfloat16*)pwl;

    const int NELEM = MROWS * EMB_C;
    dim3 gsplit(NELEM / 1024);
    dim3 gw(EMB_C / 32, EMB_C / 32), bw(32, 8);
    dim3 gg(EMB_C / 128, MROWS / 128);  // (8, 64)

    // Q projection
    split_kernel<<<gsplit, 256>>>(Q, ihi, ilo, NELEM);
    wsplit_kernel<<<gw, bw>>>(WQ, whi, wlo);
    gemm_tc_kernel<<<gg, 256>>>(ihi, ilo, whi, wlo, bQ, (float*)pq,
                                MROWS, EMB_C, EMB_C);
    // K projection
    split_kernel<<<gsplit, 256>>>(K, ihi, ilo, NELEM);
    wsplit_kernel<<<gw, bw>>>(WK, whi, wlo);
    gemm_tc_kernel<<<gg, 256>>>(ihi, ilo, whi, wlo, bK, (float*)pk,
                                MROWS, EMB_C, EMB_C);
    // V projection
    split_kernel<<<gsplit, 256>>>(V, ihi, ilo, NELEM);
    wsplit_kernel<<<gw, bw>>>(WV, whi, wlo);
    gemm_tc_kernel<<<gg, 256>>>(ihi, ilo, whi, wlo, bV, (float*)pv,
                                MROWS, EMB_C, EMB_C);

    // attention (tensor core)
    dim3 ga(L_C / 128, HEADS_C, B_C);   // (16, 16, 4)
    attn_tc_kernel<<<ga, 256>>>((const float*)pq, (const float*)pk,
                                (const float*)pv, (float*)pa);

    // O projection
    split_kernel<<<gsplit, 256>>>((const float*)pa, ihi, ilo, NELEM);
    wsplit_kernel<<<gw, bw>>>(WO, whi, wlo);
    gemm_tc_kernel<<<gg, 256>>>(ihi, ilo, whi, wlo, bO, out,
                                MROWS, EMB_C, EMB_C);
}